// round 8
// baseline (speedup 1.0000x reference)
#include <cuda_runtime.h>
#include <cstdint>

// Problem constants (fixed shapes)
#define N_NODES 50000
#define N_EDGES 1600000

constexpr int SCAN_BS = 512;
constexpr int SCAN_NB = (N_NODES + SCAN_BS - 1) / SCAN_BS;  // 98

// ---------------------------------------------------------------------------
// Scratch
// ---------------------------------------------------------------------------
__device__ float g_deg[N_NODES];
__device__ float g_dis[N_NODES];
__device__ float g_diag[N_NODES];
__device__ int   g_cnt[N_NODES];
__device__ int   g_rowptr[N_NODES + 1];
__device__ int   g_cursor[N_NODES];
__device__ int2  g_cw[N_EDGES];          // packed (col, w-bits)
__device__ int   g_bsum[SCAN_NB];
__device__ int   g_boff[SCAN_NB];
// Clenshaw buffers:
//   U = x @ [W1_0|W1_1|W1_2|W1_3]  (N x 256, slices of 64)
//   H = layer-1 output              (N x 64)
//   V = H @ [W2_0|W2_1|W2_2|W2_3]  (N x 160, slices of 40)
__device__ float g_U[(size_t)N_NODES * 256];
__device__ float g_H[(size_t)N_NODES * 64];
__device__ float g_V[(size_t)N_NODES * 160];

// ---------------------------------------------------------------------------
// Preprocessing
// ---------------------------------------------------------------------------
__global__ void k_zero_nodes() {
    int i = blockIdx.x * blockDim.x + threadIdx.x;
    if (i < N_NODES) { g_deg[i] = 0.f; g_cnt[i] = 0; }
}

__global__ void k_degree(const int* __restrict__ src, const int* __restrict__ dst,
                         const float* __restrict__ ew) {
    int e = blockIdx.x * blockDim.x + threadIdx.x;
    if (e < N_EDGES) {
        atomicAdd(&g_deg[src[e]], ew[e]);
        atomicAdd(&g_cnt[dst[e]], 1);
    }
}

__global__ void k_norm() {
    int i = blockIdx.x * blockDim.x + threadIdx.x;
    if (i < N_NODES) {
        float d = g_deg[i];
        g_dis[i]  = (d > 0.f) ? rsqrtf(fmaxf(d, 1e-12f)) : 0.f;
        g_diag[i] = (d > 0.f) ? 0.f : -1.f;
    }
}

// ---- 3-phase scan of g_cnt -> g_rowptr (exclusive), g_cursor ----
__global__ void k_scan1() {
    __shared__ int ws[SCAN_BS / 32];
    const int tid = threadIdx.x;
    const int i = blockIdx.x * SCAN_BS + tid;
    int v = (i < N_NODES) ? g_cnt[i] : 0;
#pragma unroll
    for (int off = 16; off > 0; off >>= 1)
        v += __shfl_down_sync(0xffffffffu, v, off);
    if ((tid & 31) == 0) ws[tid >> 5] = v;
    __syncthreads();
    if (tid < SCAN_BS / 32) {
        int s = ws[tid];
#pragma unroll
        for (int off = SCAN_BS / 64; off > 0; off >>= 1)
            s += __shfl_down_sync(0xffffffffu, s, off);
        if (tid == 0) g_bsum[blockIdx.x] = s;
    }
}

__global__ void k_scan2() {
    __shared__ int sm[128];
    const int tid = threadIdx.x;
    int v = (tid < SCAN_NB) ? g_bsum[tid] : 0;
    sm[tid] = v;
    __syncthreads();
#pragma unroll
    for (int off = 1; off < 128; off <<= 1) {
        int y = (tid >= off) ? sm[tid - off] : 0;
        __syncthreads();
        sm[tid] += y;
        __syncthreads();
    }
    if (tid < SCAN_NB) g_boff[tid] = sm[tid] - v;
    if (tid == 127) g_rowptr[N_NODES] = sm[127];
}

__global__ void k_scan3() {
    __shared__ int ws[SCAN_BS / 32];
    const int tid = threadIdx.x;
    const int lane = tid & 31;
    const int wid = tid >> 5;
    const int i = blockIdx.x * SCAN_BS + tid;
    int v = (i < N_NODES) ? g_cnt[i] : 0;
    int x = v;
#pragma unroll
    for (int off = 1; off < 32; off <<= 1) {
        int y = __shfl_up_sync(0xffffffffu, x, off);
        if (lane >= off) x += y;
    }
    if (lane == 31) ws[wid] = x;
    __syncthreads();
    if (wid == 0) {
        int s = (lane < SCAN_BS / 32) ? ws[lane] : 0;
#pragma unroll
        for (int off = 1; off < SCAN_BS / 32; off <<= 1) {
            int y = __shfl_up_sync(0xffffffffu, s, off);
            if (lane >= off) s += y;
        }
        if (lane < SCAN_BS / 32) ws[lane] = s;
    }
    __syncthreads();
    int excl = x - v + ((wid > 0) ? ws[wid - 1] : 0) + g_boff[blockIdx.x];
    if (i < N_NODES) { g_rowptr[i] = excl; g_cursor[i] = excl; }
}

__global__ void k_fill(const int* __restrict__ src, const int* __restrict__ dst,
                       const float* __restrict__ ew) {
    int e = blockIdx.x * blockDim.x + threadIdx.x;
    if (e < N_EDGES) {
        int s = src[e], d = dst[e];
        int pos = atomicAdd(&g_cursor[d], 1);
        float w = -g_dis[s] * ew[e] * g_dis[d];
        g_cw[pos] = make_int2(s, __float_as_int(w));
    }
}

// ---------------------------------------------------------------------------
// Clenshaw SpMM step: out = alpha * (L_hat @ in) + u [- v] [+ bias] [relu]
// Multi-row-per-warp: FEATS/4 lanes per row (float4/lane), 32/(FEATS/4) rows
// per warp. Packed (col,w) int2 loads. Loop to warp-max degree, predicated.
// ---------------------------------------------------------------------------
template <int FEATS, bool HASV, bool HASBIAS, bool RELU>
__global__ __launch_bounds__(256) void k_spmm(
        const float* __restrict__ in, int si,
        const float* __restrict__ u, int su,
        const float* __restrict__ v, int sv,
        float alpha,
        float* __restrict__ out, int so,
        const float* __restrict__ bias) {
    constexpr int LPR = FEATS / 4;   // lanes per row
    constexpr int RPW = 32 / LPR;    // rows per warp

    const int gw = (blockIdx.x * blockDim.x + threadIdx.x) >> 5;
    const int lane = threadIdx.x & 31;
    const int row_base = gw * RPW;
    if (row_base >= N_NODES) return;

    const int sub = lane / LPR;
    const int li = lane % LPR;
    const int row_t = row_base + sub;
    const bool act = (sub < RPW) && (row_t < N_NODES);
    const int row = act ? row_t : 0;

    int beg = 0, deg = 0;
    if (act) {
        beg = __ldg(&g_rowptr[row]);
        deg = __ldg(&g_rowptr[row + 1]) - beg;
    }
    const int m = __reduce_max_sync(0xffffffffu, deg);
    const int lv = li * 4;

    float a0 = 0.f, a1 = 0.f, a2 = 0.f, a3 = 0.f;

    for (int j = 0; j < m; j += 4) {
        int c[4];
        float wt[4];
#pragma unroll
        for (int t = 0; t < 4; t++) {
            const bool ok = (j + t) < deg;
            int2 cwp = make_int2(0, 0);
            if (ok) cwp = __ldg(&g_cw[beg + j + t]);
            c[t] = cwp.x;
            wt[t] = __int_as_float(cwp.y);
        }
        float4 g0 = *(const float4*)(in + (size_t)c[0] * si + lv);
        float4 g1 = *(const float4*)(in + (size_t)c[1] * si + lv);
        float4 g2 = *(const float4*)(in + (size_t)c[2] * si + lv);
        float4 g3 = *(const float4*)(in + (size_t)c[3] * si + lv);
        a0 = fmaf(wt[0], g0.x, a0); a1 = fmaf(wt[0], g0.y, a1);
        a2 = fmaf(wt[0], g0.z, a2); a3 = fmaf(wt[0], g0.w, a3);
        a0 = fmaf(wt[1], g1.x, a0); a1 = fmaf(wt[1], g1.y, a1);
        a2 = fmaf(wt[1], g1.z, a2); a3 = fmaf(wt[1], g1.w, a3);
        a0 = fmaf(wt[2], g2.x, a0); a1 = fmaf(wt[2], g2.y, a1);
        a2 = fmaf(wt[2], g2.z, a2); a3 = fmaf(wt[2], g2.w, a3);
        a0 = fmaf(wt[3], g3.x, a0); a1 = fmaf(wt[3], g3.y, a1);
        a2 = fmaf(wt[3], g3.z, a2); a3 = fmaf(wt[3], g3.w, a3);
    }

    if (!act) return;

    // diagonal term of L_hat
    {
        const float dg = g_diag[row];
        const float4 vd = *(const float4*)(in + (size_t)row * si + lv);
        a0 = fmaf(dg, vd.x, a0); a1 = fmaf(dg, vd.y, a1);
        a2 = fmaf(dg, vd.z, a2); a3 = fmaf(dg, vd.w, a3);
    }

    const float4 uu = *(const float4*)(u + (size_t)row * su + lv);
    float r0 = fmaf(alpha, a0, uu.x);
    float r1 = fmaf(alpha, a1, uu.y);
    float r2 = fmaf(alpha, a2, uu.z);
    float r3 = fmaf(alpha, a3, uu.w);
    if constexpr (HASV) {
        const float4 vv = *(const float4*)(v + (size_t)row * sv + lv);
        r0 -= vv.x; r1 -= vv.y; r2 -= vv.z; r3 -= vv.w;
    }
    if constexpr (HASBIAS) {
        const float4 bb = *(const float4*)(bias + lv);
        r0 += bb.x; r1 += bb.y; r2 += bb.z; r3 += bb.w;
    }
    if constexpr (RELU) {
        r0 = fmaxf(r0, 0.f); r1 = fmaxf(r1, 0.f);
        r2 = fmaxf(r2, 0.f); r3 = fmaxf(r3, 0.f);
    }
    *(float4*)(out + (size_t)row * so + lv) = make_float4(r0, r1, r2, r3);
}

// ---------------------------------------------------------------------------
// GEMM: out[N x M] = A[N x KD] @ Wcat[KD x M]  (W slice-remapped into SMEM)
// Thread tile 8x8: 64 FMA per 4 LDS.128 per k-step. BM=128 row tiles.
// ---------------------------------------------------------------------------
template <int KD, int M, int BM, int THREADS, int SW>
__global__ __launch_bounds__(THREADS) void k_gemm(
        const float* __restrict__ A, int lda,
        const float* __restrict__ W,
        float* __restrict__ out, int ldo) {
    constexpr int BK = 16;
    static_assert(THREADS == (M / 8) * (BM / 8), "thread mapping");
    extern __shared__ float sh[];
    float* Bs = sh;             // KD * M
    float* As = sh + KD * M;    // BK * BM, layout As[k][r]

    const int tid = threadIdx.x;

    // Stage W with slice remap: Bs[kd][s*SW+j] = W[(s*KD+kd)*SW + j]
    for (int t = tid; t < KD * M / 4; t += THREADS) {
        const int flat = t * 4;
        const int kd = flat / M;
        const int c = flat - kd * M;
        const int s = c / SW;
        const int j = c - s * SW;
        const float4 val = *(const float4*)(W + ((size_t)(s * KD + kd)) * SW + j);
        *(float4*)(&Bs[(size_t)kd * M + c]) = val;
    }

    const int cx = tid % (M / 8);
    const int ry = tid / (M / 8);     // 0 .. BM/8-1
    const int ntiles = (N_NODES + BM - 1) / BM;
    __syncthreads();

    for (int tile = blockIdx.x; tile < ntiles; tile += gridDim.x) {
        const int row0 = tile * BM;
        float acc[8][8];
#pragma unroll
        for (int j = 0; j < 8; j++)
#pragma unroll
            for (int i = 0; i < 8; i++) acc[j][i] = 0.f;

#pragma unroll 1
        for (int k0 = 0; k0 < KD; k0 += BK) {
            for (int t = tid; t < BM * BK / 4; t += THREADS) {
                const int kk4 = t & 3;
                const int r = t >> 2;
                const int row = row0 + r;
                float4 v = make_float4(0.f, 0.f, 0.f, 0.f);
                if (row < N_NODES)
                    v = *(const float4*)(A + (size_t)row * lda + k0 + kk4 * 4);
                As[(kk4 * 4 + 0) * BM + r] = v.x;
                As[(kk4 * 4 + 1) * BM + r] = v.y;
                As[(kk4 * 4 + 2) * BM + r] = v.z;
                As[(kk4 * 4 + 3) * BM + r] = v.w;
            }
            __syncthreads();
#pragma unroll
            for (int kk = 0; kk < BK; kk++) {
                const float4 aa0 = *(const float4*)(&As[kk * BM + ry * 8]);
                const float4 aa1 = *(const float4*)(&As[kk * BM + ry * 8 + 4]);
                const float4 bb0 = *(const float4*)(&Bs[(size_t)(k0 + kk) * M + cx * 8]);
                const float4 bb1 = *(const float4*)(&Bs[(size_t)(k0 + kk) * M + cx * 8 + 4]);
                const float a[8] = {aa0.x, aa0.y, aa0.z, aa0.w,
                                    aa1.x, aa1.y, aa1.z, aa1.w};
                const float b[8] = {bb0.x, bb0.y, bb0.z, bb0.w,
                                    bb1.x, bb1.y, bb1.z, bb1.w};
#pragma unroll
                for (int j = 0; j < 8; j++) {
#pragma unroll
                    for (int i = 0; i < 8; i++)
                        acc[j][i] = fmaf(a[j], b[i], acc[j][i]);
                }
            }
            __syncthreads();
        }

        const int col = cx * 8;
#pragma unroll
        for (int j = 0; j < 8; j++) {
            const int row = row0 + ry * 8 + j;
            if (row < N_NODES) {
                *(float4*)(out + (size_t)row * ldo + col) =
                    make_float4(acc[j][0], acc[j][1], acc[j][2], acc[j][3]);
                *(float4*)(out + (size_t)row * ldo + col + 4) =
                    make_float4(acc[j][4], acc[j][5], acc[j][6], acc[j][7]);
            }
        }
    }
}

// ---------------------------------------------------------------------------
// Launch (round-6 dataflow; stream/event handles are created ONCE and reused
// so graph capture does not strand fresh driver allocations)
// ---------------------------------------------------------------------------
extern "C" void kernel_launch(void* const* d_in, const int* in_sizes, int n_in,
                              void* d_out, int out_size) {
    const float* x  = (const float*)d_in[0];
    const int*   ei = (const int*)d_in[1];
    const float* ew = (const float*)d_in[2];
    const float* W1 = (const float*)d_in[3];
    const float* b1 = (const float*)d_in[4];
    const float* W2 = (const float*)d_in[5];
    const float* b2 = (const float*)d_in[6];
    const int* src = ei;
    const int* dst = ei + N_EDGES;

    float *U, *H, *V;
    cudaGetSymbolAddress((void**)&U, g_U);
    cudaGetSymbolAddress((void**)&H, g_H);
    cudaGetSymbolAddress((void**)&V, g_V);

    // GEMM configs (thread tile 8x8, BM=128)
    //  G1: U[N x 256] = x[N x 128] @ remap(W1)   KD=128,M=256,BM=128,512 thr
    //  G2: V[N x 160] = H[N x 64]  @ remap(W2)   KD=64, M=160,BM=128,320 thr
    const int smem1 = (128 * 256 + 16 * 128) * 4;   // 139264 B
    const int smem2 = (64 * 160 + 16 * 128) * 4;    // 49152 B
    cudaFuncSetAttribute((const void*)k_gemm<128, 256, 128, 512, 64>,
                         cudaFuncAttributeMaxDynamicSharedMemorySize, smem1);
    cudaFuncSetAttribute((const void*)k_gemm<64, 160, 128, 320, 40>,
                         cudaFuncAttributeMaxDynamicSharedMemorySize, smem2);

    const int ngrid = (N_NODES + 255) / 256;
    const int egrid = (N_EDGES + 255) / 256;
    const int warps64 = (N_NODES + 1) / 2;            // RPW=2
    const int sgrid64 = (warps64 * 32 + 255) / 256;
    const int warps40 = (N_NODES + 2) / 3;            // RPW=3
    const int sgrid40 = (warps40 * 32 + 255) / 256;

    // One-time creation (first call = correctness run, so these allocations
    // land inside the harness's pre-capture baseline and are reused by the
    // capture call — nothing is allocated during capture).
    static cudaStream_t s2 = nullptr;
    static cudaEvent_t evFork = nullptr, evJoin = nullptr;
    if (s2 == nullptr) {
        cudaStreamCreateWithFlags(&s2, cudaStreamNonBlocking);
        cudaEventCreateWithFlags(&evFork, cudaEventDisableTiming);
        cudaEventCreateWithFlags(&evJoin, cudaEventDisableTiming);
    }

    // --- Fork: preprocessing (CSR build) on s2, GEMM1 on main stream ---
    cudaEventRecord(evFork, 0);
    cudaStreamWaitEvent(s2, evFork, 0);

    k_zero_nodes<<<ngrid, 256, 0, s2>>>();
    k_degree<<<egrid, 256, 0, s2>>>(src, dst, ew);
    k_norm<<<ngrid, 256, 0, s2>>>();
    k_scan1<<<SCAN_NB, SCAN_BS, 0, s2>>>();
    k_scan2<<<1, 128, 0, s2>>>();
    k_scan3<<<SCAN_NB, SCAN_BS, 0, s2>>>();
    k_fill<<<egrid, 256, 0, s2>>>(src, dst, ew);
    cudaEventRecord(evJoin, s2);

    // GEMM1 concurrently on the main stream: U = x @ [W1 slices]
    k_gemm<128, 256, 128, 512, 64><<<148, 512, smem1>>>(x, 128, W1, U, 256);

    cudaStreamWaitEvent(0, evJoin, 0);   // join before first SpMM

    float* U0 = U;
    float* U1 = U + 64;
    float* U2 = U + 128;
    float* U3 = U + 192;
    // ---- Layer 1 (Clenshaw at F=64) ----
    // b2c = 2*L@U3 + U2           (overwrites U2)
    k_spmm<64, false, false, false><<<sgrid64, 256>>>(U3, 256, U2, 256, nullptr, 0,
                                                      2.f, U2, 256, nullptr);
    // b1c = 2*L@b2c + U1 - U3     (overwrites U1)
    k_spmm<64, true, false, false><<<sgrid64, 256>>>(U2, 256, U1, 256, U3, 256,
                                                     2.f, U1, 256, nullptr);
    // H = relu(L@b1c + U0 - b2c + bias1)
    k_spmm<64, true, true, true><<<sgrid64, 256>>>(U1, 256, U0, 256, U2, 256,
                                                   1.f, H, 64, b1);

    // ---- Layer 2 (Clenshaw at F=40) ----
    // V = H @ [W2 slices]
    k_gemm<64, 160, 128, 320, 40><<<148, 320, smem2>>>(H, 64, W2, V, 160);
    float* V0 = V;
    float* V1 = V + 40;
    float* V2 = V + 80;
    float* V3 = V + 120;
    // c2 = 2*L@V3 + V2            (overwrites V2)
    k_spmm<40, false, false, false><<<sgrid40, 256>>>(V3, 160, V2, 160, nullptr, 0,
                                                      2.f, V2, 160, nullptr);
    // c1 = 2*L@c2 + V1 - V3       (overwrites V1)
    k_spmm<40, true, false, false><<<sgrid40, 256>>>(V2, 160, V1, 160, V3, 160,
                                                     2.f, V1, 160, nullptr);
    // out = L@c1 + V0 - c2 + bias2
    k_spmm<40, true, true, false><<<sgrid40, 256>>>(V1, 160, V0, 160, V2, 160,
                                                    1.f, (float*)d_out, 40, b2);
}

// round 9
// speedup vs baseline: 1.0085x; 1.0085x over previous
#include <cuda_runtime.h>
#include <cstdint>

// Problem constants (fixed shapes)
#define N_NODES 50000
#define N_EDGES 1600000

constexpr int SCAN_BS = 512;
constexpr int SCAN_NB = (N_NODES + SCAN_BS - 1) / SCAN_BS;  // 98

// ---------------------------------------------------------------------------
// Scratch
// ---------------------------------------------------------------------------
__device__ float g_deg[N_NODES];
__device__ float g_dis[N_NODES];
__device__ float g_diag[N_NODES];
__device__ int   g_cnt[N_NODES];
__device__ int   g_rowptr[N_NODES + 1];
__device__ int   g_cursor[N_NODES];
__device__ int2  g_cw[N_EDGES];          // packed (col, w-bits)
__device__ int   g_bsum[SCAN_NB];
__device__ int   g_boff[SCAN_NB];
// Clenshaw buffers:
//   U = x @ [W1_0|W1_1|W1_2|W1_3]  (N x 256, slices of 64)
//   H = layer-1 output              (N x 64)
//   V = H @ [W2_0|W2_1|W2_2|W2_3]  (N x 160, slices of 40)
__device__ float g_U[(size_t)N_NODES * 256];
__device__ float g_H[(size_t)N_NODES * 64];
__device__ float g_V[(size_t)N_NODES * 160];

// ---------------------------------------------------------------------------
// Preprocessing
// ---------------------------------------------------------------------------
__global__ void k_zero_nodes() {
    int i = blockIdx.x * blockDim.x + threadIdx.x;
    if (i < N_NODES) { g_deg[i] = 0.f; g_cnt[i] = 0; }
}

__global__ void k_degree(const int* __restrict__ src, const int* __restrict__ dst,
                         const float* __restrict__ ew) {
    int e = blockIdx.x * blockDim.x + threadIdx.x;
    if (e < N_EDGES) {
        atomicAdd(&g_deg[src[e]], ew[e]);
        atomicAdd(&g_cnt[dst[e]], 1);
    }
}

// ---- scan phase 1 (per-block sums), fused with degree normalization ----
__global__ void k_scan1() {
    __shared__ int ws[SCAN_BS / 32];
    const int tid = threadIdx.x;
    const int i = blockIdx.x * SCAN_BS + tid;
    int v = 0;
    if (i < N_NODES) {
        v = g_cnt[i];
        // fused k_norm
        float d = g_deg[i];
        g_dis[i]  = (d > 0.f) ? rsqrtf(fmaxf(d, 1e-12f)) : 0.f;
        g_diag[i] = (d > 0.f) ? 0.f : -1.f;
    }
    int s = v;
#pragma unroll
    for (int off = 16; off > 0; off >>= 1)
        s += __shfl_down_sync(0xffffffffu, s, off);
    if ((tid & 31) == 0) ws[tid >> 5] = s;
    __syncthreads();
    if (tid < SCAN_BS / 32) {
        int t = ws[tid];
#pragma unroll
        for (int off = SCAN_BS / 64; off > 0; off >>= 1)
            t += __shfl_down_sync(0xffffffffu, t, off);
        if (tid == 0) g_bsum[blockIdx.x] = t;
    }
}

__global__ void k_scan2() {
    __shared__ int sm[128];
    const int tid = threadIdx.x;
    int v = (tid < SCAN_NB) ? g_bsum[tid] : 0;
    sm[tid] = v;
    __syncthreads();
#pragma unroll
    for (int off = 1; off < 128; off <<= 1) {
        int y = (tid >= off) ? sm[tid - off] : 0;
        __syncthreads();
        sm[tid] += y;
        __syncthreads();
    }
    if (tid < SCAN_NB) g_boff[tid] = sm[tid] - v;
    if (tid == 127) g_rowptr[N_NODES] = sm[127];
}

__global__ void k_scan3() {
    __shared__ int ws[SCAN_BS / 32];
    const int tid = threadIdx.x;
    const int lane = tid & 31;
    const int wid = tid >> 5;
    const int i = blockIdx.x * SCAN_BS + tid;
    int v = (i < N_NODES) ? g_cnt[i] : 0;
    int x = v;
#pragma unroll
    for (int off = 1; off < 32; off <<= 1) {
        int y = __shfl_up_sync(0xffffffffu, x, off);
        if (lane >= off) x += y;
    }
    if (lane == 31) ws[wid] = x;
    __syncthreads();
    if (wid == 0) {
        int s = (lane < SCAN_BS / 32) ? ws[lane] : 0;
#pragma unroll
        for (int off = 1; off < SCAN_BS / 32; off <<= 1) {
            int y = __shfl_up_sync(0xffffffffu, s, off);
            if (lane >= off) s += y;
        }
        if (lane < SCAN_BS / 32) ws[lane] = s;
    }
    __syncthreads();
    int excl = x - v + ((wid > 0) ? ws[wid - 1] : 0) + g_boff[blockIdx.x];
    if (i < N_NODES) { g_rowptr[i] = excl; g_cursor[i] = excl; }
}

__global__ void k_fill(const int* __restrict__ src, const int* __restrict__ dst,
                       const float* __restrict__ ew) {
    int e = blockIdx.x * blockDim.x + threadIdx.x;
    if (e < N_EDGES) {
        int s = src[e], d = dst[e];
        int pos = atomicAdd(&g_cursor[d], 1);
        float w = -g_dis[s] * ew[e] * g_dis[d];
        g_cw[pos] = make_int2(s, __float_as_int(w));
    }
}

// ---------------------------------------------------------------------------
// Clenshaw SpMM step: out = alpha * (L_hat @ in) + u [- v] [+ bias] [relu]
// Multi-row-per-warp: FEATS/4 lanes per row (float4/lane), 32/(FEATS/4) rows
// per warp. Packed (col,w) int2 loads. Loop to warp-max degree, predicated.
// ---------------------------------------------------------------------------
template <int FEATS, bool HASV, bool HASBIAS, bool RELU>
__global__ __launch_bounds__(256) void k_spmm(
        const float* __restrict__ in, int si,
        const float* __restrict__ u, int su,
        const float* __restrict__ v, int sv,
        float alpha,
        float* __restrict__ out, int so,
        const float* __restrict__ bias) {
    constexpr int LPR = FEATS / 4;   // lanes per row
    constexpr int RPW = 32 / LPR;    // rows per warp

    const int gw = (blockIdx.x * blockDim.x + threadIdx.x) >> 5;
    const int lane = threadIdx.x & 31;
    const int row_base = gw * RPW;
    if (row_base >= N_NODES) return;

    const int sub = lane / LPR;
    const int li = lane % LPR;
    const int row_t = row_base + sub;
    const bool act = (sub < RPW) && (row_t < N_NODES);
    const int row = act ? row_t : 0;

    int beg = 0, deg = 0;
    if (act) {
        beg = __ldg(&g_rowptr[row]);
        deg = __ldg(&g_rowptr[row + 1]) - beg;
    }
    const int m = __reduce_max_sync(0xffffffffu, deg);
    const int lv = li * 4;

    float a0 = 0.f, a1 = 0.f, a2 = 0.f, a3 = 0.f;

    for (int j = 0; j < m; j += 4) {
        int c[4];
        float wt[4];
#pragma unroll
        for (int t = 0; t < 4; t++) {
            const bool ok = (j + t) < deg;
            int2 cwp = make_int2(0, 0);
            if (ok) cwp = __ldg(&g_cw[beg + j + t]);
            c[t] = cwp.x;
            wt[t] = __int_as_float(cwp.y);
        }
        float4 g0 = *(const float4*)(in + (size_t)c[0] * si + lv);
        float4 g1 = *(const float4*)(in + (size_t)c[1] * si + lv);
        float4 g2 = *(const float4*)(in + (size_t)c[2] * si + lv);
        float4 g3 = *(const float4*)(in + (size_t)c[3] * si + lv);
        a0 = fmaf(wt[0], g0.x, a0); a1 = fmaf(wt[0], g0.y, a1);
        a2 = fmaf(wt[0], g0.z, a2); a3 = fmaf(wt[0], g0.w, a3);
        a0 = fmaf(wt[1], g1.x, a0); a1 = fmaf(wt[1], g1.y, a1);
        a2 = fmaf(wt[1], g1.z, a2); a3 = fmaf(wt[1], g1.w, a3);
        a0 = fmaf(wt[2], g2.x, a0); a1 = fmaf(wt[2], g2.y, a1);
        a2 = fmaf(wt[2], g2.z, a2); a3 = fmaf(wt[2], g2.w, a3);
        a0 = fmaf(wt[3], g3.x, a0); a1 = fmaf(wt[3], g3.y, a1);
        a2 = fmaf(wt[3], g3.z, a2); a3 = fmaf(wt[3], g3.w, a3);
    }

    if (!act) return;

    // diagonal term of L_hat
    {
        const float dg = g_diag[row];
        const float4 vd = *(const float4*)(in + (size_t)row * si + lv);
        a0 = fmaf(dg, vd.x, a0); a1 = fmaf(dg, vd.y, a1);
        a2 = fmaf(dg, vd.z, a2); a3 = fmaf(dg, vd.w, a3);
    }

    const float4 uu = *(const float4*)(u + (size_t)row * su + lv);
    float r0 = fmaf(alpha, a0, uu.x);
    float r1 = fmaf(alpha, a1, uu.y);
    float r2 = fmaf(alpha, a2, uu.z);
    float r3 = fmaf(alpha, a3, uu.w);
    if constexpr (HASV) {
        const float4 vv = *(const float4*)(v + (size_t)row * sv + lv);
        r0 -= vv.x; r1 -= vv.y; r2 -= vv.z; r3 -= vv.w;
    }
    if constexpr (HASBIAS) {
        const float4 bb = *(const float4*)(bias + lv);
        r0 += bb.x; r1 += bb.y; r2 += bb.z; r3 += bb.w;
    }
    if constexpr (RELU) {
        r0 = fmaxf(r0, 0.f); r1 = fmaxf(r1, 0.f);
        r2 = fmaxf(r2, 0.f); r3 = fmaxf(r3, 0.f);
    }
    *(float4*)(out + (size_t)row * so + lv) = make_float4(r0, r1, r2, r3);
}

// ---------------------------------------------------------------------------
// GEMM: out[N x M_total] = A[N x KD] @ Wcat[KD x M_total], thread tile 8x4.
// HALVES=2: single launch, even/odd CTAs own the two M-column halves (M each);
// smem holds only KD*M -> higher occupancy. W is slice-remapped into SMEM.
// ---------------------------------------------------------------------------
template <int KD, int M, int BM, int THREADS, int SW, int HALVES>
__global__ __launch_bounds__(THREADS) void k_gemm(
        const float* __restrict__ A, int lda,
        const float* __restrict__ W,
        float* __restrict__ out, int ldo) {
    constexpr int BK = 16;
    static_assert(THREADS == (M / 4) * (BM / 8), "thread mapping");
    extern __shared__ float sh[];
    float* Bs = sh;             // KD * M
    float* As = sh + KD * M;    // BK * BM, layout As[k][r]

    const int tid = threadIdx.x;

    const int half = (HALVES == 2) ? (blockIdx.x & 1) : 0;
    const float* Wh = W + (size_t)half * (M / SW) * KD * SW;
    float* outh = out + half * M;
    const int bstart = (HALVES == 2) ? (blockIdx.x >> 1) : blockIdx.x;
    const int bstride = (HALVES == 2) ? (gridDim.x >> 1) : gridDim.x;

    // Stage W with slice remap: Bs[kd][s*SW+j] = Wh[(s*KD+kd)*SW + j]
    for (int t = tid; t < KD * M / 4; t += THREADS) {
        const int flat = t * 4;
        const int kd = flat / M;
        const int c = flat - kd * M;
        const int s = c / SW;
        const int j = c - s * SW;
        const float4 val = *(const float4*)(Wh + ((size_t)(s * KD + kd)) * SW + j);
        *(float4*)(&Bs[(size_t)kd * M + c]) = val;
    }

    const int cx = tid % (M / 4);
    const int ry = tid / (M / 4);     // 0 .. BM/8-1
    const int ntiles = (N_NODES + BM - 1) / BM;
    __syncthreads();

    for (int tile = bstart; tile < ntiles; tile += bstride) {
        const int row0 = tile * BM;
        float acc[8][4];
#pragma unroll
        for (int j = 0; j < 8; j++)
#pragma unroll
            for (int i = 0; i < 4; i++) acc[j][i] = 0.f;

#pragma unroll 1
        for (int k0 = 0; k0 < KD; k0 += BK) {
            for (int t = tid; t < BM * BK / 4; t += THREADS) {
                const int kk4 = t & 3;
                const int r = t >> 2;
                const int row = row0 + r;
                float4 v = make_float4(0.f, 0.f, 0.f, 0.f);
                if (row < N_NODES)
                    v = *(const float4*)(A + (size_t)row * lda + k0 + kk4 * 4);
                As[(kk4 * 4 + 0) * BM + r] = v.x;
                As[(kk4 * 4 + 1) * BM + r] = v.y;
                As[(kk4 * 4 + 2) * BM + r] = v.z;
                As[(kk4 * 4 + 3) * BM + r] = v.w;
            }
            __syncthreads();
#pragma unroll
            for (int kk = 0; kk < BK; kk++) {
                const float4 aa0 = *(const float4*)(&As[kk * BM + ry * 8]);
                const float4 aa1 = *(const float4*)(&As[kk * BM + ry * 8 + 4]);
                const float4 bb = *(const float4*)(&Bs[(size_t)(k0 + kk) * M + cx * 4]);
                const float a[8] = {aa0.x, aa0.y, aa0.z, aa0.w,
                                    aa1.x, aa1.y, aa1.z, aa1.w};
#pragma unroll
                for (int j = 0; j < 8; j++) {
                    acc[j][0] = fmaf(a[j], bb.x, acc[j][0]);
                    acc[j][1] = fmaf(a[j], bb.y, acc[j][1]);
                    acc[j][2] = fmaf(a[j], bb.z, acc[j][2]);
                    acc[j][3] = fmaf(a[j], bb.w, acc[j][3]);
                }
            }
            __syncthreads();
        }

        const int col = cx * 4;
#pragma unroll
        for (int j = 0; j < 8; j++) {
            const int row = row0 + ry * 8 + j;
            if (row < N_NODES) {
                *(float4*)(outh + (size_t)row * ldo + col) =
                    make_float4(acc[j][0], acc[j][1], acc[j][2], acc[j][3]);
            }
        }
    }
}

// ---------------------------------------------------------------------------
// Launch (round-6 dataflow; persistent stream/event handles)
// ---------------------------------------------------------------------------
extern "C" void kernel_launch(void* const* d_in, const int* in_sizes, int n_in,
                              void* d_out, int out_size) {
    const float* x  = (const float*)d_in[0];
    const int*   ei = (const int*)d_in[1];
    const float* ew = (const float*)d_in[2];
    const float* W1 = (const float*)d_in[3];
    const float* b1 = (const float*)d_in[4];
    const float* W2 = (const float*)d_in[5];
    const float* b2 = (const float*)d_in[6];
    const int* src = ei;
    const int* dst = ei + N_EDGES;

    float *U, *H, *V;
    cudaGetSymbolAddress((void**)&U, g_U);
    cudaGetSymbolAddress((void**)&H, g_H);
    cudaGetSymbolAddress((void**)&V, g_V);

    // GEMM configs (thread tile 8x4)
    //  G1: column-split HALVES=2: each CTA half does M=128, BM=64, 256 thr
    //      smem = (128*128 + 16*64)*4 = 69632 B -> 3 CTAs/SM
    //  G2: KD=64, M=160, BM=128, 640 thr (round-6 config)
    const int smem1 = (128 * 128 + 16 * 64) * 4;    // 69632 B
    const int smem2 = (64 * 160 + 16 * 128) * 4;    // 49152 B
    cudaFuncSetAttribute((const void*)k_gemm<128, 128, 64, 256, 64, 2>,
                         cudaFuncAttributeMaxDynamicSharedMemorySize, smem1);
    cudaFuncSetAttribute((const void*)k_gemm<64, 160, 128, 640, 40, 1>,
                         cudaFuncAttributeMaxDynamicSharedMemorySize, smem2);

    const int ngrid = (N_NODES + 255) / 256;
    const int egrid = (N_EDGES + 255) / 256;
    const int warps64 = (N_NODES + 1) / 2;            // RPW=2
    const int sgrid64 = (warps64 * 32 + 255) / 256;
    const int warps40 = (N_NODES + 2) / 3;            // RPW=3
    const int sgrid40 = (warps40 * 32 + 255) / 256;

    // One-time creation (first call = correctness run, so these allocations
    // land inside the harness's pre-capture baseline and are reused by the
    // capture call — nothing is allocated during capture).
    static cudaStream_t s2 = nullptr;
    static cudaEvent_t evFork = nullptr, evJoin = nullptr;
    if (s2 == nullptr) {
        cudaStreamCreateWithFlags(&s2, cudaStreamNonBlocking);
        cudaEventCreateWithFlags(&evFork, cudaEventDisableTiming);
        cudaEventCreateWithFlags(&evJoin, cudaEventDisableTiming);
    }

    // --- Fork: preprocessing (CSR build) on s2, GEMM1 on main stream ---
    cudaEventRecord(evFork, 0);
    cudaStreamWaitEvent(s2, evFork, 0);

    k_zero_nodes<<<ngrid, 256, 0, s2>>>();
    k_degree<<<egrid, 256, 0, s2>>>(src, dst, ew);
    k_scan1<<<SCAN_NB, SCAN_BS, 0, s2>>>();   // + fused norm
    k_scan2<<<1, 128, 0, s2>>>();
    k_scan3<<<SCAN_NB, SCAN_BS, 0, s2>>>();
    k_fill<<<egrid, 256, 0, s2>>>(src, dst, ew);
    cudaEventRecord(evJoin, s2);

    // GEMM1 concurrently on the main stream: U = x @ [W1 slices]
    // (column-split single launch: 296 CTAs, even/odd = column half)
    k_gemm<128, 128, 64, 256, 64, 2><<<296, 256, smem1>>>(x, 128, W1, U, 256);

    cudaStreamWaitEvent(0, evJoin, 0);   // join before first SpMM

    float* U0 = U;
    float* U1 = U + 64;
    float* U2 = U + 128;
    float* U3 = U + 192;
    // ---- Layer 1 (Clenshaw at F=64) ----
    // b2c = 2*L@U3 + U2           (overwrites U2)
    k_spmm<64, false, false, false><<<sgrid64, 256>>>(U3, 256, U2, 256, nullptr, 0,
                                                      2.f, U2, 256, nullptr);
    // b1c = 2*L@b2c + U1 - U3     (overwrites U1)
    k_spmm<64, true, false, false><<<sgrid64, 256>>>(U2, 256, U1, 256, U3, 256,
                                                     2.f, U1, 256, nullptr);
    // H = relu(L@b1c + U0 - b2c + bias1)
    k_spmm<64, true, true, true><<<sgrid64, 256>>>(U1, 256, U0, 256, U2, 256,
                                                   1.f, H, 64, b1);

    // ---- Layer 2 (Clenshaw at F=40) ----
    // V = H @ [W2 slices]
    k_gemm<64, 160, 128, 640, 40, 1><<<148, 640, smem2>>>(H, 64, W2, V, 160);
    float* V0 = V;
    float* V1 = V + 40;
    float* V2 = V + 80;
    float* V3 = V + 120;
    // c2 = 2*L@V3 + V2            (overwrites V2)
    k_spmm<40, false, false, false><<<sgrid40, 256>>>(V3, 160, V2, 160, nullptr, 0,
                                                      2.f, V2, 160, nullptr);
    // c1 = 2*L@c2 + V1 - V3       (overwrites V1)
    k_spmm<40, true, false, false><<<sgrid40, 256>>>(V2, 160, V1, 160, V3, 160,
                                                     2.f, V1, 160, nullptr);
    // out = L@c1 + V0 - c2 + bias2
    k_spmm<40, true, true, false><<<sgrid40, 256>>>(V1, 160, V0, 160, V2, 160,
                                                    1.f, (float*)d_out, 40, b2);
}

// round 10
// speedup vs baseline: 1.1529x; 1.1431x over previous
#include <cuda_runtime.h>
#include <cuda_fp16.h>
#include <cstdint>

// Problem constants (fixed shapes)
#define N_NODES 50000
#define N_EDGES 1600000

constexpr int SCAN_BS = 512;
constexpr int SCAN_NB = (N_NODES + SCAN_BS - 1) / SCAN_BS;  // 98

// ---------------------------------------------------------------------------
// Scratch
// ---------------------------------------------------------------------------
__device__ float g_deg[N_NODES];
__device__ float g_dis[N_NODES];
__device__ float g_diag[N_NODES];
__device__ int   g_cnt[N_NODES];
__device__ int   g_rowptr[N_NODES + 1];
__device__ int   g_cursor[N_NODES];
__device__ int2  g_cw[N_EDGES];          // packed (col, w-bits)
__device__ int   g_bsum[SCAN_NB];
__device__ int   g_boff[SCAN_NB];
// Clenshaw buffers (fp32):
//   U = x @ [W1_0..3]  (N x 256), H (N x 64), V = H @ [W2_0..3] (N x 160)
__device__ float g_U[(size_t)N_NODES * 256];
__device__ float g_H[(size_t)N_NODES * 64];
__device__ float g_V[(size_t)N_NODES * 160];
// fp16 gather mirrors (ping-pong), stride = FEATS (64 or 40)
__device__ __half g_F16a[(size_t)N_NODES * 64];
__device__ __half g_F16b[(size_t)N_NODES * 64];

// ---------------------------------------------------------------------------
// Preprocessing
// ---------------------------------------------------------------------------
__global__ void k_zero_nodes() {
    int i = blockIdx.x * blockDim.x + threadIdx.x;
    if (i < N_NODES) { g_deg[i] = 0.f; g_cnt[i] = 0; }
}

__global__ void k_degree(const int* __restrict__ src, const int* __restrict__ dst,
                         const float* __restrict__ ew) {
    int e = blockIdx.x * blockDim.x + threadIdx.x;
    if (e < N_EDGES) {
        atomicAdd(&g_deg[src[e]], ew[e]);
        atomicAdd(&g_cnt[dst[e]], 1);
    }
}

// ---- scan phase 1 (per-block sums), fused with degree normalization ----
__global__ void k_scan1() {
    __shared__ int ws[SCAN_BS / 32];
    const int tid = threadIdx.x;
    const int i = blockIdx.x * SCAN_BS + tid;
    int v = 0;
    if (i < N_NODES) {
        v = g_cnt[i];
        float d = g_deg[i];
        g_dis[i]  = (d > 0.f) ? rsqrtf(fmaxf(d, 1e-12f)) : 0.f;
        g_diag[i] = (d > 0.f) ? 0.f : -1.f;
    }
    int s = v;
#pragma unroll
    for (int off = 16; off > 0; off >>= 1)
        s += __shfl_down_sync(0xffffffffu, s, off);
    if ((tid & 31) == 0) ws[tid >> 5] = s;
    __syncthreads();
    if (tid < SCAN_BS / 32) {
        int t = ws[tid];
#pragma unroll
        for (int off = SCAN_BS / 64; off > 0; off >>= 1)
            t += __shfl_down_sync(0xffffffffu, t, off);
        if (tid == 0) g_bsum[blockIdx.x] = t;
    }
}

__global__ void k_scan2() {
    __shared__ int sm[128];
    const int tid = threadIdx.x;
    int v = (tid < SCAN_NB) ? g_bsum[tid] : 0;
    sm[tid] = v;
    __syncthreads();
#pragma unroll
    for (int off = 1; off < 128; off <<= 1) {
        int y = (tid >= off) ? sm[tid - off] : 0;
        __syncthreads();
        sm[tid] += y;
        __syncthreads();
    }
    if (tid < SCAN_NB) g_boff[tid] = sm[tid] - v;
    if (tid == 127) g_rowptr[N_NODES] = sm[127];
}

__global__ void k_scan3() {
    __shared__ int ws[SCAN_BS / 32];
    const int tid = threadIdx.x;
    const int lane = tid & 31;
    const int wid = tid >> 5;
    const int i = blockIdx.x * SCAN_BS + tid;
    int v = (i < N_NODES) ? g_cnt[i] : 0;
    int x = v;
#pragma unroll
    for (int off = 1; off < 32; off <<= 1) {
        int y = __shfl_up_sync(0xffffffffu, x, off);
        if (lane >= off) x += y;
    }
    if (lane == 31) ws[wid] = x;
    __syncthreads();
    if (wid == 0) {
        int s = (lane < SCAN_BS / 32) ? ws[lane] : 0;
#pragma unroll
        for (int off = 1; off < SCAN_BS / 32; off <<= 1) {
            int y = __shfl_up_sync(0xffffffffu, s, off);
            if (lane >= off) s += y;
        }
        if (lane < SCAN_BS / 32) ws[lane] = s;
    }
    __syncthreads();
    int excl = x - v + ((wid > 0) ? ws[wid - 1] : 0) + g_boff[blockIdx.x];
    if (i < N_NODES) { g_rowptr[i] = excl; g_cursor[i] = excl; }
}

__global__ void k_fill(const int* __restrict__ src, const int* __restrict__ dst,
                       const float* __restrict__ ew) {
    int e = blockIdx.x * blockDim.x + threadIdx.x;
    if (e < N_EDGES) {
        int s = src[e], d = dst[e];
        int pos = atomicAdd(&g_cursor[d], 1);
        float w = -g_dis[s] * ew[e] * g_dis[d];
        g_cw[pos] = make_int2(s, __float_as_int(w));
    }
}

// ---------------------------------------------------------------------------
// Clenshaw SpMM step: out = alpha * (L_hat @ in16) + u [- v] [+ bias] [relu]
// Gathered operand is fp16 (traffic-halving); accumulation + row-local fp32.
// FEATS/8 lanes per row (uint4 = 8 halves per lane); RPW = 32/LPR rows/warp.
//   FEATS=64: LPR=8, RPW=4.  FEATS=40: LPR=5, RPW=6 (30 active lanes).
// out16 != nullptr: also write fp16 mirror of out (stride FEATS).
// ---------------------------------------------------------------------------
template <int FEATS, bool HASV, bool HASBIAS, bool RELU>
__global__ __launch_bounds__(256) void k_spmm(
        const __half* __restrict__ in16,
        const float* __restrict__ u, int su,
        const float* __restrict__ v, int sv,
        float alpha,
        float* __restrict__ out, int so,
        __half* __restrict__ out16,
        const float* __restrict__ bias) {
    constexpr int LPR = FEATS / 8;   // lanes per row
    constexpr int RPW = 32 / LPR;    // rows per warp

    const int gw = (blockIdx.x * blockDim.x + threadIdx.x) >> 5;
    const int lane = threadIdx.x & 31;
    const int row_base = gw * RPW;
    if (row_base >= N_NODES) return;

    const int sub = lane / LPR;
    const int li = lane % LPR;
    const bool act = (sub < RPW) && (row_base + sub < N_NODES);
    const int row = act ? (row_base + sub) : 0;

    int beg = 0, deg = 0;
    if (act) {
        beg = __ldg(&g_rowptr[row]);
        deg = __ldg(&g_rowptr[row + 1]) - beg;
    }
    const int m = __reduce_max_sync(0xffffffffu, deg);
    const int lv = li * 8;

    float a[8];
#pragma unroll
    for (int i = 0; i < 8; i++) a[i] = 0.f;

    for (int j = 0; j < m; j += 4) {
        int cc[4];
        float wt[4];
#pragma unroll
        for (int t = 0; t < 4; t++) {
            int2 cwp = make_int2(0, 0);
            if ((j + t) < deg) cwp = __ldg(&g_cw[beg + j + t]);
            cc[t] = cwp.x;
            wt[t] = __int_as_float(cwp.y);
        }
        uint4 gv[4];
#pragma unroll
        for (int t = 0; t < 4; t++)
            gv[t] = *(const uint4*)(in16 + (size_t)cc[t] * FEATS + lv);
#pragma unroll
        for (int t = 0; t < 4; t++) {
            const __half2* hp = reinterpret_cast<const __half2*>(&gv[t]);
            const float2 f0 = __half22float2(hp[0]);
            const float2 f1 = __half22float2(hp[1]);
            const float2 f2 = __half22float2(hp[2]);
            const float2 f3 = __half22float2(hp[3]);
            a[0] = fmaf(wt[t], f0.x, a[0]); a[1] = fmaf(wt[t], f0.y, a[1]);
            a[2] = fmaf(wt[t], f1.x, a[2]); a[3] = fmaf(wt[t], f1.y, a[3]);
            a[4] = fmaf(wt[t], f2.x, a[4]); a[5] = fmaf(wt[t], f2.y, a[5]);
            a[6] = fmaf(wt[t], f3.x, a[6]); a[7] = fmaf(wt[t], f3.y, a[7]);
        }
    }

    if (!act) return;

    // diagonal term of L_hat (from the same fp16 operand)
    {
        const float dg = g_diag[row];
        const uint4 gv = *(const uint4*)(in16 + (size_t)row * FEATS + lv);
        const __half2* hp = reinterpret_cast<const __half2*>(&gv);
        const float2 f0 = __half22float2(hp[0]);
        const float2 f1 = __half22float2(hp[1]);
        const float2 f2 = __half22float2(hp[2]);
        const float2 f3 = __half22float2(hp[3]);
        a[0] = fmaf(dg, f0.x, a[0]); a[1] = fmaf(dg, f0.y, a[1]);
        a[2] = fmaf(dg, f1.x, a[2]); a[3] = fmaf(dg, f1.y, a[3]);
        a[4] = fmaf(dg, f2.x, a[4]); a[5] = fmaf(dg, f2.y, a[5]);
        a[6] = fmaf(dg, f3.x, a[6]); a[7] = fmaf(dg, f3.y, a[7]);
    }

    float r[8];
    {
        const float4 u0 = *(const float4*)(u + (size_t)row * su + lv);
        const float4 u1 = *(const float4*)(u + (size_t)row * su + lv + 4);
        r[0] = fmaf(alpha, a[0], u0.x); r[1] = fmaf(alpha, a[1], u0.y);
        r[2] = fmaf(alpha, a[2], u0.z); r[3] = fmaf(alpha, a[3], u0.w);
        r[4] = fmaf(alpha, a[4], u1.x); r[5] = fmaf(alpha, a[5], u1.y);
        r[6] = fmaf(alpha, a[6], u1.z); r[7] = fmaf(alpha, a[7], u1.w);
    }
    if constexpr (HASV) {
        const float4 v0 = *(const float4*)(v + (size_t)row * sv + lv);
        const float4 v1 = *(const float4*)(v + (size_t)row * sv + lv + 4);
        r[0] -= v0.x; r[1] -= v0.y; r[2] -= v0.z; r[3] -= v0.w;
        r[4] -= v1.x; r[5] -= v1.y; r[6] -= v1.z; r[7] -= v1.w;
    }
    if constexpr (HASBIAS) {
        const float4 b0 = *(const float4*)(bias + lv);
        const float4 b1 = *(const float4*)(bias + lv + 4);
        r[0] += b0.x; r[1] += b0.y; r[2] += b0.z; r[3] += b0.w;
        r[4] += b1.x; r[5] += b1.y; r[6] += b1.z; r[7] += b1.w;
    }
    if constexpr (RELU) {
#pragma unroll
        for (int i = 0; i < 8; i++) r[i] = fmaxf(r[i], 0.f);
    }

    *(float4*)(out + (size_t)row * so + lv) = make_float4(r[0], r[1], r[2], r[3]);
    *(float4*)(out + (size_t)row * so + lv + 4) = make_float4(r[4], r[5], r[6], r[7]);

    if (out16 != nullptr) {
        __half2 h0 = __float22half2_rn(make_float2(r[0], r[1]));
        __half2 h1 = __float22half2_rn(make_float2(r[2], r[3]));
        __half2 h2 = __float22half2_rn(make_float2(r[4], r[5]));
        __half2 h3 = __float22half2_rn(make_float2(r[6], r[7]));
        uint4 pk;
        pk.x = *reinterpret_cast<unsigned*>(&h0);
        pk.y = *reinterpret_cast<unsigned*>(&h1);
        pk.z = *reinterpret_cast<unsigned*>(&h2);
        pk.w = *reinterpret_cast<unsigned*>(&h3);
        *(uint4*)(out16 + (size_t)row * FEATS + lv) = pk;
    }
}

// ---------------------------------------------------------------------------
// GEMM: out[N x M] = A[N x KD] @ Wcat[KD x M] (W slice-remapped into SMEM).
// Thread tile 8x4 (round-6 proven config). Columns >= F16OFF also written as
// fp16 into out16 (stride F16W) — the slice-3 gather mirror.
// ---------------------------------------------------------------------------
template <int KD, int M, int BM, int THREADS, int SW, int F16OFF, int F16W>
__global__ __launch_bounds__(THREADS) void k_gemm(
        const float* __restrict__ A, int lda,
        const float* __restrict__ W,
        float* __restrict__ out, int ldo,
        __half* __restrict__ out16) {
    constexpr int BK = 16;
    static_assert(THREADS == (M / 4) * (BM / 8), "thread mapping");
    extern __shared__ float sh[];
    float* Bs = sh;             // KD * M
    float* As = sh + KD * M;    // BK * BM, layout As[k][r]

    const int tid = threadIdx.x;

    // Stage W with slice remap: Bs[kd][s*SW+j] = W[(s*KD+kd)*SW + j]
    for (int t = tid; t < KD * M / 4; t += THREADS) {
        const int flat = t * 4;
        const int kd = flat / M;
        const int c = flat - kd * M;
        const int s = c / SW;
        const int j = c - s * SW;
        const float4 val = *(const float4*)(W + ((size_t)(s * KD + kd)) * SW + j);
        *(float4*)(&Bs[(size_t)kd * M + c]) = val;
    }

    const int cx = tid % (M / 4);
    const int ry = tid / (M / 4);     // 0 .. BM/8-1
    const int ntiles = (N_NODES + BM - 1) / BM;
    __syncthreads();

    for (int tile = blockIdx.x; tile < ntiles; tile += gridDim.x) {
        const int row0 = tile * BM;
        float acc[8][4];
#pragma unroll
        for (int j = 0; j < 8; j++)
#pragma unroll
            for (int i = 0; i < 4; i++) acc[j][i] = 0.f;

#pragma unroll 1
        for (int k0 = 0; k0 < KD; k0 += BK) {
            for (int t = tid; t < BM * BK / 4; t += THREADS) {
                const int kk4 = t & 3;
                const int r = t >> 2;
                const int row = row0 + r;
                float4 v = make_float4(0.f, 0.f, 0.f, 0.f);
                if (row < N_NODES)
                    v = *(const float4*)(A + (size_t)row * lda + k0 + kk4 * 4);
                As[(kk4 * 4 + 0) * BM + r] = v.x;
                As[(kk4 * 4 + 1) * BM + r] = v.y;
                As[(kk4 * 4 + 2) * BM + r] = v.z;
                As[(kk4 * 4 + 3) * BM + r] = v.w;
            }
            __syncthreads();
#pragma unroll
            for (int kk = 0; kk < BK; kk++) {
                const float4 aa0 = *(const float4*)(&As[kk * BM + ry * 8]);
                const float4 aa1 = *(const float4*)(&As[kk * BM + ry * 8 + 4]);
                const float4 bb = *(const float4*)(&Bs[(size_t)(k0 + kk) * M + cx * 4]);
                const float a[8] = {aa0.x, aa0.y, aa0.z, aa0.w,
                                    aa1.x, aa1.y, aa1.z, aa1.w};
#pragma unroll
                for (int j = 0; j < 8; j++) {
                    acc[j][0] = fmaf(a[j], bb.x, acc[j][0]);
                    acc[j][1] = fmaf(a[j], bb.y, acc[j][1]);
                    acc[j][2] = fmaf(a[j], bb.z, acc[j][2]);
                    acc[j][3] = fmaf(a[j], bb.w, acc[j][3]);
                }
            }
            __syncthreads();
        }

        const int col = cx * 4;
#pragma unroll
        for (int j = 0; j < 8; j++) {
            const int row = row0 + ry * 8 + j;
            if (row < N_NODES) {
                *(float4*)(out + (size_t)row * ldo + col) =
                    make_float4(acc[j][0], acc[j][1], acc[j][2], acc[j][3]);
                if (F16W > 0 && col >= F16OFF) {
                    __half2 h0 = __float22half2_rn(make_float2(acc[j][0], acc[j][1]));
                    __half2 h1 = __float22half2_rn(make_float2(acc[j][2], acc[j][3]));
                    uint2 pk;
                    pk.x = *reinterpret_cast<unsigned*>(&h0);
                    pk.y = *reinterpret_cast<unsigned*>(&h1);
                    *(uint2*)(out16 + (size_t)row * F16W + (col - F16OFF)) = pk;
                }
            }
        }
    }
}

// ---------------------------------------------------------------------------
// Launch (round-6 dataflow; persistent stream/event handles)
// ---------------------------------------------------------------------------
extern "C" void kernel_launch(void* const* d_in, const int* in_sizes, int n_in,
                              void* d_out, int out_size) {
    const float* x  = (const float*)d_in[0];
    const int*   ei = (const int*)d_in[1];
    const float* ew = (const float*)d_in[2];
    const float* W1 = (const float*)d_in[3];
    const float* b1 = (const float*)d_in[4];
    const float* W2 = (const float*)d_in[5];
    const float* b2 = (const float*)d_in[6];
    const int* src = ei;
    const int* dst = ei + N_EDGES;

    float *U, *H, *V;
    __half *bufA, *bufB;
    cudaGetSymbolAddress((void**)&U, g_U);
    cudaGetSymbolAddress((void**)&H, g_H);
    cudaGetSymbolAddress((void**)&V, g_V);
    cudaGetSymbolAddress((void**)&bufA, g_F16a);
    cudaGetSymbolAddress((void**)&bufB, g_F16b);

    // GEMM configs (round-6 proven 8x4 tiles)
    //  G1: KD=128, M=256, BM=64, 512 thr; fp16 mirror of cols 192..255
    //  G2: KD=64,  M=160, BM=128, 640 thr; fp16 mirror of cols 120..159
    const int smem1 = (128 * 256 + 16 * 64) * 4;    // 135168 B
    const int smem2 = (64 * 160 + 16 * 128) * 4;    // 49152 B
    cudaFuncSetAttribute((const void*)k_gemm<128, 256, 64, 512, 64, 192, 64>,
                         cudaFuncAttributeMaxDynamicSharedMemorySize, smem1);
    cudaFuncSetAttribute((const void*)k_gemm<64, 160, 128, 640, 40, 120, 40>,
                         cudaFuncAttributeMaxDynamicSharedMemorySize, smem2);

    const int ngrid = (N_NODES + 255) / 256;
    const int egrid = (N_EDGES + 255) / 256;
    // SpMM grids: F=64 -> RPW=4; F=40 -> RPW=6
    const int warps64 = (N_NODES + 3) / 4;
    const int sgrid64 = (warps64 + 7) / 8;           // 8 warps per 256-thr block
    const int warps40 = (N_NODES + 5) / 6;
    const int sgrid40 = (warps40 + 7) / 8;

    // One-time creation (first call = correctness run, so these allocations
    // land inside the harness's pre-capture baseline and are reused by the
    // capture call — nothing is allocated during capture).
    static cudaStream_t s2 = nullptr;
    static cudaEvent_t evFork = nullptr, evJoin = nullptr;
    if (s2 == nullptr) {
        cudaStreamCreateWithFlags(&s2, cudaStreamNonBlocking);
        cudaEventCreateWithFlags(&evFork, cudaEventDisableTiming);
        cudaEventCreateWithFlags(&evJoin, cudaEventDisableTiming);
    }

    // --- Fork: preprocessing (CSR build) on s2, GEMM1 on main stream ---
    cudaEventRecord(evFork, 0);
    cudaStreamWaitEvent(s2, evFork, 0);

    k_zero_nodes<<<ngrid, 256, 0, s2>>>();
    k_degree<<<egrid, 256, 0, s2>>>(src, dst, ew);
    k_scan1<<<SCAN_NB, SCAN_BS, 0, s2>>>();   // + fused norm
    k_scan2<<<1, 128, 0, s2>>>();
    k_scan3<<<SCAN_NB, SCAN_BS, 0, s2>>>();
    k_fill<<<egrid, 256, 0, s2>>>(src, dst, ew);
    cudaEventRecord(evJoin, s2);

    // GEMM1 concurrently on the main stream: U = x @ [W1 slices], U3 -> bufA
    k_gemm<128, 256, 64, 512, 64, 192, 64><<<148, 512, smem1>>>(
        x, 128, W1, U, 256, bufA);

    cudaStreamWaitEvent(0, evJoin, 0);   // join before first SpMM

    float* U0 = U;
    float* U1 = U + 64;
    float* U2 = U + 128;
    float* U3 = U + 192;
    // ---- Layer 1 (Clenshaw at F=64) ----
    // b2c = 2*L@U3 + U2    (overwrites U2; fp16 mirror -> bufB)
    k_spmm<64, false, false, false><<<sgrid64, 256>>>(
        bufA, U2, 256, nullptr, 0, 2.f, U2, 256, bufB, nullptr);
    // b1c = 2*L@b2c + U1 - U3   (overwrites U1; fp16 mirror -> bufA)
    k_spmm<64, true, false, false><<<sgrid64, 256>>>(
        bufB, U1, 256, U3, 256, 2.f, U1, 256, bufA, nullptr);
    // H = relu(L@b1c + U0 - b2c + bias1)
    k_spmm<64, true, true, true><<<sgrid64, 256>>>(
        bufA, U0, 256, U2, 256, 1.f, H, 64, nullptr, b1);

    // ---- Layer 2 (Clenshaw at F=40) ----
    // V = H @ [W2 slices], V3 -> bufA
    k_gemm<64, 160, 128, 640, 40, 120, 40><<<148, 640, smem2>>>(
        H, 64, W2, V, 160, bufA);
    float* V0 = V;
    float* V1 = V + 40;
    float* V2 = V + 80;
    float* V3 = V + 120;
    // c2 = 2*L@V3 + V2    (overwrites V2; fp16 mirror -> bufB)
    k_spmm<40, false, false, false><<<sgrid40, 256>>>(
        bufA, V2, 160, nullptr, 0, 2.f, V2, 160, bufB, nullptr);
    // c1 = 2*L@c2 + V1 - V3   (overwrites V1; fp16 mirror -> bufA)
    k_spmm<40, true, false, false><<<sgrid40, 256>>>(
        bufB, V1, 160, V3, 160, 2.f, V1, 160, bufA, nullptr);
    // out = L@c1 + V0 - c2 + bias2
    k_spmm<40, true, true, false><<<sgrid40, 256>>>(
        bufA, V0, 160, V2, 160, 1.f, (float*)d_out, 40, nullptr, b2);
}

// round 11
// speedup vs baseline: 1.2222x; 1.0601x over previous
#include <cuda_runtime.h>
#include <cuda_fp16.h>
#include <mma.h>
#include <cstdint>

using namespace nvcuda;

// Problem constants (fixed shapes)
#define N_NODES 50000
#define N_EDGES 1600000
constexpr int NPAD = 50048;              // padded to 64-row multiple for wmma

constexpr int SCAN_BS = 512;
constexpr int SCAN_NB = (N_NODES + SCAN_BS - 1) / SCAN_BS;  // 98

// ---------------------------------------------------------------------------
// Scratch
// ---------------------------------------------------------------------------
__device__ float g_deg[N_NODES];
__device__ float g_dis[N_NODES];
__device__ float g_diag[N_NODES];
__device__ int   g_cnt[N_NODES];
__device__ int   g_rowptr[N_NODES + 1];
__device__ int   g_cursor[N_NODES];
__device__ int2  g_cw[N_EDGES];          // packed (col, w-bits)
__device__ int   g_bsum[SCAN_NB];
__device__ int   g_boff[SCAN_NB];
// Clenshaw buffers (fp32, row-padded to NPAD):
__device__ float g_U[(size_t)NPAD * 256];
__device__ float g_H[(size_t)NPAD * 64];
__device__ float g_V[(size_t)NPAD * 160];
// fp16 operands
__device__ __half g_Xh[(size_t)NPAD * 128];    // x in fp16
__device__ __half g_Hh[(size_t)NPAD * 64];     // H in fp16 (GEMM2 input)
__device__ __half g_W1h[128 * 256];            // W1 remapped, fp16
__device__ __half g_W2h[64 * 160];             // W2 remapped, fp16
// fp16 gather mirrors (ping-pong), stride = FEATS (64 or 40)
__device__ __half g_F16a[(size_t)N_NODES * 64];
__device__ __half g_F16b[(size_t)N_NODES * 64];

// ---------------------------------------------------------------------------
// Preprocessing
// ---------------------------------------------------------------------------
__global__ void k_zero_nodes() {
    int i = blockIdx.x * blockDim.x + threadIdx.x;
    if (i < N_NODES) { g_deg[i] = 0.f; g_cnt[i] = 0; }
}

__global__ void k_degree(const int* __restrict__ src, const int* __restrict__ dst,
                         const float* __restrict__ ew) {
    int e = blockIdx.x * blockDim.x + threadIdx.x;
    if (e < N_EDGES) {
        atomicAdd(&g_deg[src[e]], ew[e]);
        atomicAdd(&g_cnt[dst[e]], 1);
    }
}

// ---- scan phase 1 (per-block sums), fused with degree normalization ----
__global__ void k_scan1() {
    __shared__ int ws[SCAN_BS / 32];
    const int tid = threadIdx.x;
    const int i = blockIdx.x * SCAN_BS + tid;
    int v = 0;
    if (i < N_NODES) {
        v = g_cnt[i];
        float d = g_deg[i];
        g_dis[i]  = (d > 0.f) ? rsqrtf(fmaxf(d, 1e-12f)) : 0.f;
        g_diag[i] = (d > 0.f) ? 0.f : -1.f;
    }
    int s = v;
#pragma unroll
    for (int off = 16; off > 0; off >>= 1)
        s += __shfl_down_sync(0xffffffffu, s, off);
    if ((tid & 31) == 0) ws[tid >> 5] = s;
    __syncthreads();
    if (tid < SCAN_BS / 32) {
        int t = ws[tid];
#pragma unroll
        for (int off = SCAN_BS / 64; off > 0; off >>= 1)
            t += __shfl_down_sync(0xffffffffu, t, off);
        if (tid == 0) g_bsum[blockIdx.x] = t;
    }
}

__global__ void k_scan2() {
    __shared__ int sm[128];
    const int tid = threadIdx.x;
    int v = (tid < SCAN_NB) ? g_bsum[tid] : 0;
    sm[tid] = v;
    __syncthreads();
#pragma unroll
    for (int off = 1; off < 128; off <<= 1) {
        int y = (tid >= off) ? sm[tid - off] : 0;
        __syncthreads();
        sm[tid] += y;
        __syncthreads();
    }
    if (tid < SCAN_NB) g_boff[tid] = sm[tid] - v;
    if (tid == 127) g_rowptr[N_NODES] = sm[127];
}

__global__ void k_scan3() {
    __shared__ int ws[SCAN_BS / 32];
    const int tid = threadIdx.x;
    const int lane = tid & 31;
    const int wid = tid >> 5;
    const int i = blockIdx.x * SCAN_BS + tid;
    int v = (i < N_NODES) ? g_cnt[i] : 0;
    int x = v;
#pragma unroll
    for (int off = 1; off < 32; off <<= 1) {
        int y = __shfl_up_sync(0xffffffffu, x, off);
        if (lane >= off) x += y;
    }
    if (lane == 31) ws[wid] = x;
    __syncthreads();
    if (wid == 0) {
        int s = (lane < SCAN_BS / 32) ? ws[lane] : 0;
#pragma unroll
        for (int off = 1; off < SCAN_BS / 32; off <<= 1) {
            int y = __shfl_up_sync(0xffffffffu, s, off);
            if (lane >= off) s += y;
        }
        if (lane < SCAN_BS / 32) ws[lane] = s;
    }
    __syncthreads();
    int excl = x - v + ((wid > 0) ? ws[wid - 1] : 0) + g_boff[blockIdx.x];
    if (i < N_NODES) { g_rowptr[i] = excl; g_cursor[i] = excl; }
}

__global__ void k_fill(const int* __restrict__ src, const int* __restrict__ dst,
                       const float* __restrict__ ew) {
    int e = blockIdx.x * blockDim.x + threadIdx.x;
    if (e < N_EDGES) {
        int s = src[e], d = dst[e];
        int pos = atomicAdd(&g_cursor[d], 1);
        float w = -g_dis[s] * ew[e] * g_dis[d];
        g_cw[pos] = make_int2(s, __float_as_int(w));
    }
}

// ---------------------------------------------------------------------------
// fp16 conversions
// ---------------------------------------------------------------------------
__device__ __forceinline__ uint4 pack8(const float4 f0, const float4 f1) {
    __half2 h0 = __float22half2_rn(make_float2(f0.x, f0.y));
    __half2 h1 = __float22half2_rn(make_float2(f0.z, f0.w));
    __half2 h2 = __float22half2_rn(make_float2(f1.x, f1.y));
    __half2 h3 = __float22half2_rn(make_float2(f1.z, f1.w));
    uint4 pk;
    pk.x = *reinterpret_cast<unsigned*>(&h0);
    pk.y = *reinterpret_cast<unsigned*>(&h1);
    pk.z = *reinterpret_cast<unsigned*>(&h2);
    pk.w = *reinterpret_cast<unsigned*>(&h3);
    return pk;
}

// x (N x 128 fp32) -> g_Xh (NPAD x 128 fp16, pad rows zero)
__global__ void k_cvt_x(const float* __restrict__ x) {
    const int i = blockIdx.x * blockDim.x + threadIdx.x;  // per 8 elems
    if (i >= NPAD * 128 / 8) return;
    const int row = i >> 4;
    uint4 pk = make_uint4(0, 0, 0, 0);
    if (row < N_NODES) {
        const float4 f0 = ((const float4*)x)[i * 2];
        const float4 f1 = ((const float4*)x)[i * 2 + 1];
        pk = pack8(f0, f1);
    }
    ((uint4*)g_Xh)[i] = pk;
}

// W (NS slices of KD x SW) -> Wh[kd][s*SW+j], fp16
template <int KD, int MTOT, int SW>
__global__ void k_cvt_w(const float* __restrict__ W, __half* __restrict__ Wh) {
    const int t = blockIdx.x * blockDim.x + threadIdx.x;
    if (t >= KD * MTOT) return;
    const int kd = t / MTOT;
    const int c = t - kd * MTOT;
    const int s = c / SW;
    const int j = c - s * SW;
    Wh[t] = __float2half_rn(W[((size_t)(s * KD + kd)) * SW + j]);
}

// zero pad rows of g_Hh (rows N_NODES .. NPAD)
__global__ void k_pad_hh() {
    const int t = blockIdx.x * blockDim.x + threadIdx.x;
    const int total = (NPAD - N_NODES) * 64;
    if (t < total) g_Hh[(size_t)N_NODES * 64 + t] = __float2half_rn(0.f);
}

// fp32 slice -> fp16 mirror (row stride ss -> dense FEATS)
template <int FEATS>
__global__ void k_mirror(const float* __restrict__ src, int ss,
                         __half* __restrict__ dst) {
    constexpr int GPR = FEATS / 8;    // uint4 groups per row
    const int i = blockIdx.x * blockDim.x + threadIdx.x;
    if (i >= N_NODES * GPR) return;
    const int row = i / GPR;
    const int g = i - row * GPR;
    const float4 f0 = *(const float4*)(src + (size_t)row * ss + g * 8);
    const float4 f1 = *(const float4*)(src + (size_t)row * ss + g * 8 + 4);
    *(uint4*)(dst + (size_t)row * FEATS + g * 8) = pack8(f0, f1);
}

// ---------------------------------------------------------------------------
// Clenshaw SpMM step: out = alpha * (L_hat @ in16) + u [- v] [+ bias] [relu]
// Gathered operand fp16; accumulation + row-local fp32.
// ---------------------------------------------------------------------------
template <int FEATS, bool HASV, bool HASBIAS, bool RELU>
__global__ __launch_bounds__(256) void k_spmm(
        const __half* __restrict__ in16,
        const float* __restrict__ u, int su,
        const float* __restrict__ v, int sv,
        float alpha,
        float* __restrict__ out, int so,
        __half* __restrict__ out16,
        const float* __restrict__ bias) {
    constexpr int LPR = FEATS / 8;   // lanes per row
    constexpr int RPW = 32 / LPR;    // rows per warp

    const int gw = (blockIdx.x * blockDim.x + threadIdx.x) >> 5;
    const int lane = threadIdx.x & 31;
    const int row_base = gw * RPW;
    if (row_base >= N_NODES) return;

    const int sub = lane / LPR;
    const int li = lane % LPR;
    const bool act = (sub < RPW) && (row_base + sub < N_NODES);
    const int row = act ? (row_base + sub) : 0;

    int beg = 0, deg = 0;
    if (act) {
        beg = __ldg(&g_rowptr[row]);
        deg = __ldg(&g_rowptr[row + 1]) - beg;
    }
    const int m = __reduce_max_sync(0xffffffffu, deg);
    const int lv = li * 8;

    float a[8];
#pragma unroll
    for (int i = 0; i < 8; i++) a[i] = 0.f;

    for (int j = 0; j < m; j += 4) {
        int cc[4];
        float wt[4];
#pragma unroll
        for (int t = 0; t < 4; t++) {
            int2 cwp = make_int2(0, 0);
            if ((j + t) < deg) cwp = __ldg(&g_cw[beg + j + t]);
            cc[t] = cwp.x;
            wt[t] = __int_as_float(cwp.y);
        }
        uint4 gv[4];
#pragma unroll
        for (int t = 0; t < 4; t++)
            gv[t] = *(const uint4*)(in16 + (size_t)cc[t] * FEATS + lv);
#pragma unroll
        for (int t = 0; t < 4; t++) {
            const __half2* hp = reinterpret_cast<const __half2*>(&gv[t]);
            const float2 f0 = __half22float2(hp[0]);
            const float2 f1 = __half22float2(hp[1]);
            const float2 f2 = __half22float2(hp[2]);
            const float2 f3 = __half22float2(hp[3]);
            a[0] = fmaf(wt[t], f0.x, a[0]); a[1] = fmaf(wt[t], f0.y, a[1]);
            a[2] = fmaf(wt[t], f1.x, a[2]); a[3] = fmaf(wt[t], f1.y, a[3]);
            a[4] = fmaf(wt[t], f2.x, a[4]); a[5] = fmaf(wt[t], f2.y, a[5]);
            a[6] = fmaf(wt[t], f3.x, a[6]); a[7] = fmaf(wt[t], f3.y, a[7]);
        }
    }

    if (!act) return;

    // diagonal term
    {
        const float dg = g_diag[row];
        const uint4 gv = *(const uint4*)(in16 + (size_t)row * FEATS + lv);
        const __half2* hp = reinterpret_cast<const __half2*>(&gv);
        const float2 f0 = __half22float2(hp[0]);
        const float2 f1 = __half22float2(hp[1]);
        const float2 f2 = __half22float2(hp[2]);
        const float2 f3 = __half22float2(hp[3]);
        a[0] = fmaf(dg, f0.x, a[0]); a[1] = fmaf(dg, f0.y, a[1]);
        a[2] = fmaf(dg, f1.x, a[2]); a[3] = fmaf(dg, f1.y, a[3]);
        a[4] = fmaf(dg, f2.x, a[4]); a[5] = fmaf(dg, f2.y, a[5]);
        a[6] = fmaf(dg, f3.x, a[6]); a[7] = fmaf(dg, f3.y, a[7]);
    }

    float r[8];
    {
        const float4 u0 = *(const float4*)(u + (size_t)row * su + lv);
        const float4 u1 = *(const float4*)(u + (size_t)row * su + lv + 4);
        r[0] = fmaf(alpha, a[0], u0.x); r[1] = fmaf(alpha, a[1], u0.y);
        r[2] = fmaf(alpha, a[2], u0.z); r[3] = fmaf(alpha, a[3], u0.w);
        r[4] = fmaf(alpha, a[4], u1.x); r[5] = fmaf(alpha, a[5], u1.y);
        r[6] = fmaf(alpha, a[6], u1.z); r[7] = fmaf(alpha, a[7], u1.w);
    }
    if constexpr (HASV) {
        const float4 v0 = *(const float4*)(v + (size_t)row * sv + lv);
        const float4 v1 = *(const float4*)(v + (size_t)row * sv + lv + 4);
        r[0] -= v0.x; r[1] -= v0.y; r[2] -= v0.z; r[3] -= v0.w;
        r[4] -= v1.x; r[5] -= v1.y; r[6] -= v1.z; r[7] -= v1.w;
    }
    if constexpr (HASBIAS) {
        const float4 b0 = *(const float4*)(bias + lv);
        const float4 b1 = *(const float4*)(bias + lv + 4);
        r[0] += b0.x; r[1] += b0.y; r[2] += b0.z; r[3] += b0.w;
        r[4] += b1.x; r[5] += b1.y; r[6] += b1.z; r[7] += b1.w;
    }
    if constexpr (RELU) {
#pragma unroll
        for (int i = 0; i < 8; i++) r[i] = fmaxf(r[i], 0.f);
    }

    *(float4*)(out + (size_t)row * so + lv) = make_float4(r[0], r[1], r[2], r[3]);
    *(float4*)(out + (size_t)row * so + lv + 4) = make_float4(r[4], r[5], r[6], r[7]);

    if (out16 != nullptr) {
        *(uint4*)(out16 + (size_t)row * FEATS + lv) =
            pack8(make_float4(r[0], r[1], r[2], r[3]),
                  make_float4(r[4], r[5], r[6], r[7]));
    }
}

// ---------------------------------------------------------------------------
// fp16 tensor-core GEMM (wmma): out[NPAD x MTOT] = A[NPAD x KD] @ Bh[KD x MTOT]
// CTA: 256 thr = 8 warps (4 row groups x 2 col groups), BM=64 rows, BN cols.
// HALVES: column splits of MTOT handled by even/odd CTA index.
// ---------------------------------------------------------------------------
template <int KD, int MTOT, int BN, int HALVES>
__global__ __launch_bounds__(256) void k_gemm16(
        const __half* __restrict__ A,
        const __half* __restrict__ Bh,
        float* __restrict__ out, int ldo) {
    constexpr int BM = 64;
    constexpr int WCOL = BN / 2;          // cols per warp group
    constexpr int NFRAG = WCOL / 16;      // fragments per warp
    extern __shared__ char shraw[];
    __half* Bs = reinterpret_cast<__half*>(shraw);   // KD x BN
    __half* As = Bs + KD * BN;                        // BM x KD

    const int tid = threadIdx.x;
    const int wid = tid >> 5;
    const int half_id = (HALVES == 2) ? (blockIdx.x & 1) : 0;
    const int c0 = half_id * BN;
    const int bstart = (HALVES == 2) ? (blockIdx.x >> 1) : blockIdx.x;
    const int bstride = (HALVES == 2) ? (gridDim.x >> 1) : gridDim.x;

    // stage B block (KD x BN) from Bh (row-major KD x MTOT)
    for (int t = tid; t < KD * BN / 8; t += 256) {
        const int idx = t * 8;
        const int kd = idx / BN;
        const int c = idx - kd * BN;
        *(uint4*)(Bs + (size_t)kd * BN + c) =
            *(const uint4*)(Bh + (size_t)kd * MTOT + c0 + c);
    }
    __syncthreads();

    const int wr = wid >> 1;      // 0..3
    const int wc = wid & 1;       // 0..1
    const int ntiles = NPAD / BM;

    for (int tile = bstart; tile < ntiles; tile += bstride) {
        const int row0 = tile * BM;
        // stage A tile (BM x KD)
        for (int t = tid; t < BM * KD / 8; t += 256) {
            const int idx = t * 8;
            const int r = idx / KD;
            const int k = idx - r * KD;
            *(uint4*)(As + (size_t)r * KD + k) =
                *(const uint4*)(A + (size_t)(row0 + r) * KD + k);
        }
        __syncthreads();

        wmma::fragment<wmma::accumulator, 16, 16, 16, float> acc[NFRAG];
#pragma unroll
        for (int f = 0; f < NFRAG; f++) wmma::fill_fragment(acc[f], 0.f);

#pragma unroll
        for (int k0 = 0; k0 < KD; k0 += 16) {
            wmma::fragment<wmma::matrix_a, 16, 16, 16, __half, wmma::row_major> af;
            wmma::load_matrix_sync(af, As + (size_t)(wr * 16) * KD + k0, KD);
#pragma unroll
            for (int f = 0; f < NFRAG; f++) {
                wmma::fragment<wmma::matrix_b, 16, 16, 16, __half, wmma::row_major> bf;
                wmma::load_matrix_sync(bf, Bs + (size_t)k0 * BN + wc * WCOL + f * 16, BN);
                wmma::mma_sync(acc[f], af, bf, acc[f]);
            }
        }

#pragma unroll
        for (int f = 0; f < NFRAG; f++) {
            wmma::store_matrix_sync(
                out + (size_t)(row0 + wr * 16) * ldo + c0 + wc * WCOL + f * 16,
                acc[f], ldo, wmma::mem_row_major);
        }
        __syncthreads();
    }
}

// ---------------------------------------------------------------------------
// Launch
// ---------------------------------------------------------------------------
extern "C" void kernel_launch(void* const* d_in, const int* in_sizes, int n_in,
                              void* d_out, int out_size) {
    const float* x  = (const float*)d_in[0];
    const int*   ei = (const int*)d_in[1];
    const float* ew = (const float*)d_in[2];
    const float* W1 = (const float*)d_in[3];
    const float* b1 = (const float*)d_in[4];
    const float* W2 = (const float*)d_in[5];
    const float* b2 = (const float*)d_in[6];
    const int* src = ei;
    const int* dst = ei + N_EDGES;

    float *U, *H, *V;
    __half *bufA, *bufB, *Xh, *Hh, *W1h, *W2h;
    cudaGetSymbolAddress((void**)&U, g_U);
    cudaGetSymbolAddress((void**)&H, g_H);
    cudaGetSymbolAddress((void**)&V, g_V);
    cudaGetSymbolAddress((void**)&bufA, g_F16a);
    cudaGetSymbolAddress((void**)&bufB, g_F16b);
    cudaGetSymbolAddress((void**)&Xh, g_Xh);
    cudaGetSymbolAddress((void**)&Hh, g_Hh);
    cudaGetSymbolAddress((void**)&W1h, g_W1h);
    cudaGetSymbolAddress((void**)&W2h, g_W2h);

    // GEMM smem: G1 (128x128 B + 64x128 A)*2 = 49152; G2 (64x160 + 64x64)*2 = 28672
    const int smem1 = (128 * 128 + 64 * 128) * 2;
    const int smem2 = (64 * 160 + 64 * 64) * 2;
    cudaFuncSetAttribute((const void*)k_gemm16<128, 256, 128, 2>,
                         cudaFuncAttributeMaxDynamicSharedMemorySize, smem1);
    cudaFuncSetAttribute((const void*)k_gemm16<64, 160, 160, 1>,
                         cudaFuncAttributeMaxDynamicSharedMemorySize, smem2);

    const int ngrid = (N_NODES + 255) / 256;
    const int egrid = (N_EDGES + 255) / 256;
    const int warps64 = (N_NODES + 3) / 4;           // RPW=4
    const int sgrid64 = (warps64 + 7) / 8;
    const int warps40 = (N_NODES + 5) / 6;           // RPW=6
    const int sgrid40 = (warps40 + 7) / 8;

    static cudaStream_t s2 = nullptr;
    static cudaEvent_t evFork = nullptr, evJoin = nullptr;
    if (s2 == nullptr) {
        cudaStreamCreateWithFlags(&s2, cudaStreamNonBlocking);
        cudaEventCreateWithFlags(&evFork, cudaEventDisableTiming);
        cudaEventCreateWithFlags(&evJoin, cudaEventDisableTiming);
    }

    // --- Fork: preprocessing + W2/Hh-pad prep on s2; fp16 GEMM1 path on main ---
    cudaEventRecord(evFork, 0);
    cudaStreamWaitEvent(s2, evFork, 0);

    k_zero_nodes<<<ngrid, 256, 0, s2>>>();
    k_degree<<<egrid, 256, 0, s2>>>(src, dst, ew);
    k_scan1<<<SCAN_NB, SCAN_BS, 0, s2>>>();
    k_scan2<<<1, 128, 0, s2>>>();
    k_scan3<<<SCAN_NB, SCAN_BS, 0, s2>>>();
    k_fill<<<egrid, 256, 0, s2>>>(src, dst, ew);
    k_cvt_w<64, 160, 40><<<(64 * 160 + 255) / 256, 256, 0, s2>>>(W2, W2h);
    k_pad_hh<<<((NPAD - N_NODES) * 64 + 255) / 256, 256, 0, s2>>>();
    cudaEventRecord(evJoin, s2);

    // main: convert x + W1, tensor-core GEMM1, U3 mirror
    k_cvt_x<<<(NPAD * 16 + 255) / 256, 256>>>(x);
    k_cvt_w<128, 256, 64><<<(128 * 256 + 255) / 256, 256>>>(W1, W1h);
    k_gemm16<128, 256, 128, 2><<<592, 256, smem1>>>(Xh, W1h, U, 256);
    k_mirror<64><<<(N_NODES * 8 + 255) / 256, 256>>>(U + 192, 256, bufA);

    cudaStreamWaitEvent(0, evJoin, 0);   // join before first SpMM

    float* U0 = U;
    float* U1 = U + 64;
    float* U2 = U + 128;
    // ---- Layer 1 (Clenshaw at F=64) ----
    // b2c = 2*L@U3 + U2    (overwrites U2; fp16 mirror -> bufB)
    k_spmm<64, false, false, false><<<sgrid64, 256>>>(
        bufA, U2, 256, nullptr, 0, 2.f, U2, 256, bufB, nullptr);
    // b1c = 2*L@b2c + U1 - U3   (overwrites U1; fp16 mirror -> bufA)
    k_spmm<64, true, false, false><<<sgrid64, 256>>>(
        bufB, U1, 256, U + 192, 256, 2.f, U1, 256, bufA, nullptr);
    // H = relu(L@b1c + U0 - b2c + bias1)  (fp16 mirror -> Hh for GEMM2)
    k_spmm<64, true, true, true><<<sgrid64, 256>>>(
        bufA, U0, 256, U2, 256, 1.f, H, 64, Hh, b1);

    // ---- Layer 2 (Clenshaw at F=40) ----
    // V = Hh @ [W2 slices]  (tensor-core), V3 mirror -> bufA
    k_gemm16<64, 160, 160, 1><<<782, 256, smem2>>>(Hh, W2h, V, 160);
    k_mirror<40><<<(N_NODES * 5 + 255) / 256, 256>>>(V + 120, 160, bufA);

    float* V0 = V;
    float* V1 = V + 40;
    float* V2 = V + 80;
    // c2 = 2*L@V3 + V2    (overwrites V2; fp16 mirror -> bufB)
    k_spmm<40, false, false, false><<<sgrid40, 256>>>(
        bufA, V2, 160, nullptr, 0, 2.f, V2, 160, bufB, nullptr);
    // c1 = 2*L@c2 + V1 - V3   (overwrites V1; fp16 mirror -> bufA)
    k_spmm<40, true, false, false><<<sgrid40, 256>>>(
        bufB, V1, 160, V + 120, 160, 2.f, V1, 160, bufA, nullptr);
    // out = L@c1 + V0 - c2 + bias2
    k_spmm<40, true, true, false><<<sgrid40, 256>>>(
        bufA, V0, 160, V2, 160, 1.f, (float*)d_out, 40, nullptr, b2);
}